// round 15
// baseline (speedup 1.0000x reference)
#include <cuda_runtime.h>
#include <cuda_bf16.h>

// Problem constants
#define NN 2048
#define DD 128
#define HH 64

typedef unsigned long long u64;
typedef union { u64 v; float2 f; } uf2;

// ---------- scratch (device globals; no allocation allowed) ----------
__device__ float g_pi [NN * HH];   // agent @ W1a
__device__ float g_pjt[NN * HH];   // agent @ W1b + task @ W1c + b1
__device__ int   g_count = 0;      // producer-completion counter
__device__ int   g_done  = 0;      // CTA-exit counter (for reset)

#define NPROD 512                  // producer CTAs (4 rows each)

// ---------- packed f32x2 helpers (sm_100+) ----------
__device__ __forceinline__ u64 f2add(u64 a, u64 b) {
    u64 r; asm("add.rn.f32x2 %0, %1, %2;" : "=l"(r) : "l"(a), "l"(b)); return r;
}
__device__ __forceinline__ u64 f2fma(u64 a, u64 b, u64 c) {
    u64 r; asm("fma.rn.f32x2 %0, %1, %2, %3;" : "=l"(r) : "l"(a), "l"(b), "l"(c)); return r;
}

// ---------- fused kernel ----------
// CTA tile 64x64, 256 threads, thread tile 4x4, occ 4 (R11-proven mainloop).
// Producer phase: bids < NPROD compute 4 rows of g_pi/g_pjt each, then a
// device-wide atomic barrier releases all CTAs. 592 resident slots >= 512
// producers -> all producers are wave-1 resident -> no deadlock.
#define TI 64
#define TJ 64
#define PSTRIDE 66               // pad: conflict-free LDS.64 across tx

// projection scratch overlays the pi_s region (1408 floats < 4224)
struct ProjScratch {
    float zs[4][DD];     // 512
    float zt[DD];        // 128
    float ptp[4][HH];    // 256
    float psum[4][HH*2]; // 512
};

__global__ __launch_bounds__(256, 4) void fused_kernel(const float* __restrict__ z,
                                                       const float* __restrict__ W1,
                                                       const float* __restrict__ b1,
                                                       const float* __restrict__ W2,
                                                       const float* __restrict__ b2,
                                                       const float* __restrict__ eps,
                                                       float* __restrict__ out) {
    extern __shared__ float smem[];
    float* pi_s  = smem;                        // 64 * 66
    float* pjt_s = smem + TI * PSTRIDE;         // 64 * 66
    float* c_s   = pjt_s + TJ * PSTRIDE;        // 64 (W2)
    float* eps_s = c_s + HH;                    // 64 * 64

    int tid = threadIdx.x;
    int tx = tid & 15, ty = tid >> 4;
    int it0 = blockIdx.y * TI;
    int jt0 = blockIdx.x * TJ;
    int bid = blockIdx.y * gridDim.x + blockIdx.x;

    // ---- eps tile prefetch FIRST (latency hidden behind projection/barrier) ----
#pragma unroll
    for (int it = 0; it < 4; it++) {
        int idx = tid + 256 * it;
        int row = idx >> 4;
        int col = (idx & 15) << 2;
        unsigned dst = (unsigned)__cvta_generic_to_shared(&eps_s[row * TJ + col]);
        const float* src = eps + (u64)(it0 + row) * NN + jt0 + col;
        asm volatile("cp.async.ca.shared.global [%0], [%1], 16;" :: "r"(dst), "l"(src));
    }
    asm volatile("cp.async.commit_group;");
    if (tid < HH) c_s[tid] = W2[tid];

    // ================= producer phase =================
    if (bid < NPROD) {
        ProjScratch* S = (ProjScratch*)pi_s;
        int hp  = tid & 31;
        int r   = (tid >> 5) & 3;
        int kh  = tid >> 7;
        int row_base = bid * 4;

        if (tid < 128) {
            int rr = tid >> 5, c = (tid & 31) << 2;
            *(float4*)&S->zs[rr][c] = *(const float4*)&z[(row_base + rr) * DD + c];
        }
        if (tid >= 128 && tid < 160)
            *(float4*)&S->zt[(tid - 128) << 2] = *(const float4*)&z[NN * DD + ((tid - 128) << 2)];
        __syncthreads();

        {
            int h = tid & 63, chunk = tid >> 6;
            const float* w = W1 + (2 * DD + chunk * 32) * HH + h;
            float s = 0.f;
#pragma unroll 8
            for (int k = 0; k < 32; k++) s = fmaf(S->zt[chunk * 32 + k], w[k * HH], s);
            S->ptp[chunk][h] = s;
        }

        float2 pa = {0.f, 0.f}, pb = {0.f, 0.f};
        {
            const float* wA = W1 + (kh * 64) * HH + 2 * hp;
            const float* wB = W1 + (DD + kh * 64) * HH + 2 * hp;
            const float* zr = &S->zs[r][kh * 64];
#pragma unroll 8
            for (int k = 0; k < 64; k++) {
                float2 wa = *(const float2*)(wA + k * HH);
                float2 wb = *(const float2*)(wB + k * HH);
                float zv = zr[k];
                pa.x = fmaf(zv, wa.x, pa.x);  pa.y = fmaf(zv, wa.y, pa.y);
                pb.x = fmaf(zv, wb.x, pb.x);  pb.y = fmaf(zv, wb.y, pb.y);
            }
        }
        if (kh == 1) {
            *(float2*)&S->psum[r][4 * hp]     = pa;
            *(float2*)&S->psum[r][4 * hp + 2] = pb;
        }
        __syncthreads();

        if (kh == 0) {
            float2 pa1 = *(const float2*)&S->psum[r][4 * hp];
            float2 pb1 = *(const float2*)&S->psum[r][4 * hp + 2];
            pa.x += pa1.x;  pa.y += pa1.y;
            pb.x += pb1.x;  pb.y += pb1.y;

            float ptx = b1[2 * hp]     + S->ptp[0][2 * hp]     + S->ptp[1][2 * hp]
                      + S->ptp[2][2 * hp] + S->ptp[3][2 * hp];
            float pty = b1[2 * hp + 1] + S->ptp[0][2 * hp + 1] + S->ptp[1][2 * hp + 1]
                      + S->ptp[2][2 * hp + 1] + S->ptp[3][2 * hp + 1];

            int gr = row_base + r;
            *(float2*)&g_pi[gr * HH + 2 * hp] = pa;
            pb.x += ptx;  pb.y += pty;
            *(float2*)&g_pjt[gr * HH + 2 * hp] = pb;
        }
        __syncthreads();
        __threadfence();                       // publish stores (all threads)
        if (tid == 0) atomicAdd(&g_count, 1);  // signal producer done
    }

    // ================= device-wide barrier =================
    if (tid == 0) {
        while (atomicAdd(&g_count, 0) < NPROD) __nanosleep(64);
    }
    __syncthreads();
    __threadfence();   // acquire side

    // ================= consumer phase (R11 mainloop) =================
    // stage pi tile (float2 into padded stride)
    for (int idx = tid; idx < TI * HH / 2; idx += 256) {
        int r = idx >> 5;
        int c = (idx & 31) << 1;
        *(float2*)&pi_s[r * PSTRIDE + c] = *(const float2*)&g_pi[(it0 + r) * HH + c];
    }
    // stage pjt tile
    for (int idx = tid; idx < TJ * HH / 2; idx += 256) {
        int r = idx >> 5;
        int c = (idx & 31) << 1;
        *(float2*)&pjt_s[r * PSTRIDE + c] = *(const float2*)&g_pjt[(jt0 + r) * HH + c];
    }
    __syncthreads();

    u64 acc[4][4];
#pragma unroll
    for (int r = 0; r < 4; r++)
#pragma unroll
        for (int q = 0; q < 4; q++) acc[r][q] = 0ull;

#pragma unroll 4
    for (int hp = 0; hp < HH / 2; hp++) {
        u64 c2 = *(const u64*)&c_s[2 * hp];
        u64 a[4], b[4];
#pragma unroll
        for (int r = 0; r < 4; r++)
            a[r] = *(const u64*)&pi_s[(ty + 16 * r) * PSTRIDE + 2 * hp];
#pragma unroll
        for (int q = 0; q < 4; q++)
            b[q] = *(const u64*)&pjt_s[(tx + 16 * q) * PSTRIDE + 2 * hp];
#pragma unroll
        for (int r = 0; r < 4; r++) {
#pragma unroll
            for (int q = 0; q < 4; q++) {
                uf2 t;
                t.v = f2add(a[r], b[q]);               // FADD2 (fma pipe)
                t.f.x = fmaxf(t.f.x, 0.f);             // FMNMX (alu pipe)
                t.f.y = fmaxf(t.f.y, 0.f);             // FMNMX (alu pipe)
                acc[r][q] = f2fma(t.v, c2, acc[r][q]); // FFMA2 (fma pipe)
            }
        }
    }

    // eps tile must be fully landed before reading
    asm volatile("cp.async.wait_group 0;");
    __syncthreads();

    float b2v = b2[0];
#pragma unroll
    for (int r = 0; r < 4; r++) {
#pragma unroll
        for (int q = 0; q < 4; q++) {
            uf2 s; s.v = acc[r][q];
            float w = s.f.x + s.f.y + b2v;
            int i = it0 + ty + 16 * r;
            int j = jt0 + tx + 16 * q;
            float e = eps_s[(ty + 16 * r) * TJ + (tx + 16 * q)] + 1e-8f;
            // sigmoid(w + log e - log(1-e)) = e / (e + exp(-w)*(1-e))
            float qe = __expf(-w);
            float d  = fmaf(-qe, e, qe) + e;
            out[(u64)i * NN + j] = __fdividef(e, d);
        }
    }

    // ---- reset counters for next (graph-replayed) launch ----
    __syncthreads();
    if (tid == 0) {
        int d = atomicAdd(&g_done, 1);
        if (d == (int)(gridDim.x * gridDim.y) - 1) {
            g_count = 0;
            g_done  = 0;
            __threadfence();
        }
    }
}

// ---------- launch ----------
extern "C" void kernel_launch(void* const* d_in, const int* in_sizes, int n_in,
                              void* d_out, int out_size) {
    const float* z   = (const float*)d_in[0];   // (2049, 128)
    const float* W1  = (const float*)d_in[1];   // (384, 64)
    const float* b1  = (const float*)d_in[2];   // (64,)
    const float* W2  = (const float*)d_in[3];   // (64, 1)
    const float* b2  = (const float*)d_in[4];   // (1,)
    const float* eps = (const float*)d_in[5];   // (2048, 2048)
    float* out = (float*)d_out;                 // (2048, 2048)

    size_t smem_bytes = ((TI + TJ) * PSTRIDE + HH + TI * TJ) * sizeof(float); // 50432 B
    cudaFuncSetAttribute(fused_kernel, cudaFuncAttributeMaxDynamicSharedMemorySize,
                         (int)smem_bytes);
    dim3 grid(NN / TJ, NN / TI);   // 32 x 32 = 1024 CTAs
    fused_kernel<<<grid, 256, smem_bytes>>>(z, W1, b1, W2, b2, eps, out);
}

// round 17
// speedup vs baseline: 1.0487x; 1.0487x over previous
#include <cuda_runtime.h>
#include <cuda_bf16.h>

// Problem constants
#define NN 2048
#define DD 128
#define HH 64

typedef unsigned long long u64;
typedef union { u64 v; float2 f; } uf2;

// ---------- scratch (device globals; no allocation allowed) ----------
__device__ float g_pi [NN * HH];   // agent @ W1a
__device__ float g_pjt[NN * HH];   // agent @ W1b + task @ W1c + b1
__device__ int   g_count = 0;      // producer-completion counter
__device__ volatile int g_flag = 0; // release flag (set by last producer)
__device__ int   g_done  = 0;      // CTA-exit counter (for reset)

#define NPROD 512                  // producer CTAs (4 rows each); <= 592 wave-1 slots

// ---------- packed f32x2 helpers (sm_100+) ----------
__device__ __forceinline__ u64 f2add(u64 a, u64 b) {
    u64 r; asm("add.rn.f32x2 %0, %1, %2;" : "=l"(r) : "l"(a), "l"(b)); return r;
}
__device__ __forceinline__ u64 f2fma(u64 a, u64 b, u64 c) {
    u64 r; asm("fma.rn.f32x2 %0, %1, %2, %3;" : "=l"(r) : "l"(a), "l"(b), "l"(c)); return r;
}

// ---------- fused kernel ----------
#define TI 64
#define TJ 64
#define PSTRIDE 66               // pad: conflict-free LDS.64 across tx

// projection scratch overlays the pi_s region (1408 floats < 4224)
struct ProjScratch {
    float zs[4][DD];     // 512
    float zt[DD];        // 128
    float ptp[4][HH];    // 256
    float psum[4][HH*2]; // 512
};

__global__ __launch_bounds__(256, 4) void fused_kernel(const float* __restrict__ z,
                                                       const float* __restrict__ W1,
                                                       const float* __restrict__ b1,
                                                       const float* __restrict__ W2,
                                                       const float* __restrict__ b2,
                                                       const float* __restrict__ eps,
                                                       float* __restrict__ out) {
    extern __shared__ float smem[];
    float* pi_s  = smem;                        // 64 * 66
    float* pjt_s = smem + TI * PSTRIDE;         // 64 * 66
    float* c_s   = pjt_s + TJ * PSTRIDE;        // 64 (W2)
    float* eps_s = c_s + HH;                    // 64 * 64

    int tid = threadIdx.x;
    int tx = tid & 15, ty = tid >> 4;
    int it0 = blockIdx.y * TI;
    int jt0 = blockIdx.x * TJ;
    int bid = blockIdx.y * gridDim.x + blockIdx.x;

    // ---- eps tile prefetch FIRST (latency hidden behind projection/barrier) ----
#pragma unroll
    for (int it = 0; it < 4; it++) {
        int idx = tid + 256 * it;
        int row = idx >> 4;
        int col = (idx & 15) << 2;
        unsigned dst = (unsigned)__cvta_generic_to_shared(&eps_s[row * TJ + col]);
        const float* src = eps + (u64)(it0 + row) * NN + jt0 + col;
        asm volatile("cp.async.ca.shared.global [%0], [%1], 16;" :: "r"(dst), "l"(src));
    }
    asm volatile("cp.async.commit_group;");
    if (tid < HH) c_s[tid] = W2[tid];

    // ================= producer phase =================
    if (bid < NPROD) {
        ProjScratch* S = (ProjScratch*)pi_s;
        int hp  = tid & 31;
        int r   = (tid >> 5) & 3;
        int kh  = tid >> 7;
        int row_base = bid * 4;

        if (tid < 128) {
            int rr = tid >> 5, c = (tid & 31) << 2;
            *(float4*)&S->zs[rr][c] = *(const float4*)&z[(row_base + rr) * DD + c];
        }
        if (tid >= 128 && tid < 160)
            *(float4*)&S->zt[(tid - 128) << 2] = *(const float4*)&z[NN * DD + ((tid - 128) << 2)];
        __syncthreads();

        {
            int h = tid & 63, chunk = tid >> 6;
            const float* w = W1 + (2 * DD + chunk * 32) * HH + h;
            float s = 0.f;
#pragma unroll 8
            for (int k = 0; k < 32; k++) s = fmaf(S->zt[chunk * 32 + k], w[k * HH], s);
            S->ptp[chunk][h] = s;
        }

        float2 pa = {0.f, 0.f}, pb = {0.f, 0.f};
        {
            const float* wA = W1 + (kh * 64) * HH + 2 * hp;
            const float* wB = W1 + (DD + kh * 64) * HH + 2 * hp;
            const float* zr = &S->zs[r][kh * 64];
#pragma unroll 8
            for (int k = 0; k < 64; k++) {
                float2 wa = *(const float2*)(wA + k * HH);
                float2 wb = *(const float2*)(wB + k * HH);
                float zv = zr[k];
                pa.x = fmaf(zv, wa.x, pa.x);  pa.y = fmaf(zv, wa.y, pa.y);
                pb.x = fmaf(zv, wb.x, pb.x);  pb.y = fmaf(zv, wb.y, pb.y);
            }
        }
        if (kh == 1) {
            *(float2*)&S->psum[r][4 * hp]     = pa;
            *(float2*)&S->psum[r][4 * hp + 2] = pb;
        }
        __syncthreads();

        if (kh == 0) {
            float2 pa1 = *(const float2*)&S->psum[r][4 * hp];
            float2 pb1 = *(const float2*)&S->psum[r][4 * hp + 2];
            pa.x += pa1.x;  pa.y += pa1.y;
            pb.x += pb1.x;  pb.y += pb1.y;

            float ptx = b1[2 * hp]     + S->ptp[0][2 * hp]     + S->ptp[1][2 * hp]
                      + S->ptp[2][2 * hp] + S->ptp[3][2 * hp];
            float pty = b1[2 * hp + 1] + S->ptp[0][2 * hp + 1] + S->ptp[1][2 * hp + 1]
                      + S->ptp[2][2 * hp + 1] + S->ptp[3][2 * hp + 1];

            int gr = row_base + r;
            *(float2*)&g_pi[gr * HH + 2 * hp] = pa;
            pb.x += ptx;  pb.y += pty;
            *(float2*)&g_pjt[gr * HH + 2 * hp] = pb;
        }
        __syncthreads();
        __threadfence();                       // publish stores
        if (tid == 0) {
            int old = atomicAdd(&g_count, 1);  // one RMW per producer CTA (512 total)
            if (old == NPROD - 1) g_flag = 1;  // volatile store releases waiters
        }
    }

    // ================= device-wide barrier (flag poll, no atomic storm) ====
    if (tid == 0) {
        while (g_flag == 0) __nanosleep(128);  // volatile L2 load, broadcast-friendly
    }
    __syncthreads();
    __threadfence();   // acquire side

    // ================= consumer phase (R11 mainloop) =================
    for (int idx = tid; idx < TI * HH / 2; idx += 256) {
        int r = idx >> 5;
        int c = (idx & 31) << 1;
        *(float2*)&pi_s[r * PSTRIDE + c] = *(const float2*)&g_pi[(it0 + r) * HH + c];
    }
    for (int idx = tid; idx < TJ * HH / 2; idx += 256) {
        int r = idx >> 5;
        int c = (idx & 31) << 1;
        *(float2*)&pjt_s[r * PSTRIDE + c] = *(const float2*)&g_pjt[(jt0 + r) * HH + c];
    }
    __syncthreads();

    u64 acc[4][4];
#pragma unroll
    for (int r = 0; r < 4; r++)
#pragma unroll
        for (int q = 0; q < 4; q++) acc[r][q] = 0ull;

#pragma unroll 4
    for (int hp = 0; hp < HH / 2; hp++) {
        u64 c2 = *(const u64*)&c_s[2 * hp];
        u64 a[4], b[4];
#pragma unroll
        for (int r = 0; r < 4; r++)
            a[r] = *(const u64*)&pi_s[(ty + 16 * r) * PSTRIDE + 2 * hp];
#pragma unroll
        for (int q = 0; q < 4; q++)
            b[q] = *(const u64*)&pjt_s[(tx + 16 * q) * PSTRIDE + 2 * hp];
#pragma unroll
        for (int r = 0; r < 4; r++) {
#pragma unroll
            for (int q = 0; q < 4; q++) {
                uf2 t;
                t.v = f2add(a[r], b[q]);               // FADD2 (fma pipe)
                t.f.x = fmaxf(t.f.x, 0.f);             // FMNMX (alu pipe)
                t.f.y = fmaxf(t.f.y, 0.f);             // FMNMX (alu pipe)
                acc[r][q] = f2fma(t.v, c2, acc[r][q]); // FFMA2 (fma pipe)
            }
        }
    }

    // eps tile must be fully landed before reading
    asm volatile("cp.async.wait_group 0;");
    __syncthreads();

    float b2v = b2[0];
#pragma unroll
    for (int r = 0; r < 4; r++) {
#pragma unroll
        for (int q = 0; q < 4; q++) {
            uf2 s; s.v = acc[r][q];
            float w = s.f.x + s.f.y + b2v;
            int i = it0 + ty + 16 * r;
            int j = jt0 + tx + 16 * q;
            float e = eps_s[(ty + 16 * r) * TJ + (tx + 16 * q)] + 1e-8f;
            // sigmoid(w + log e - log(1-e)) = e / (e + exp(-w)*(1-e))
            float qe = __expf(-w);
            float d  = fmaf(-qe, e, qe) + e;
            out[(u64)i * NN + j] = __fdividef(e, d);
        }
    }

    // ---- reset counters for next (graph-replayed) launch ----
    __syncthreads();
    if (tid == 0) {
        int d = atomicAdd(&g_done, 1);
        if (d == (int)(gridDim.x * gridDim.y) - 1) {
            g_count = 0;
            g_flag  = 0;
            g_done  = 0;
            __threadfence();
        }
    }
}

// ---------- launch ----------
extern "C" void kernel_launch(void* const* d_in, const int* in_sizes, int n_in,
                              void* d_out, int out_size) {
    const float* z   = (const float*)d_in[0];   // (2049, 128)
    const float* W1  = (const float*)d_in[1];   // (384, 64)
    const float* b1  = (const float*)d_in[2];   // (64,)
    const float* W2  = (const float*)d_in[3];   // (64, 1)
    const float* b2  = (const float*)d_in[4];   // (1,)
    const float* eps = (const float*)d_in[5];   // (2048, 2048)
    float* out = (float*)d_out;                 // (2048, 2048)

    size_t smem_bytes = ((TI + TJ) * PSTRIDE + HH + TI * TJ) * sizeof(float); // 50432 B
    cudaFuncSetAttribute(fused_kernel, cudaFuncAttributeMaxDynamicSharedMemorySize,
                         (int)smem_bytes);
    dim3 grid(NN / TJ, NN / TI);   // 32 x 32 = 1024 CTAs
    fused_kernel<<<grid, 256, smem_bytes>>>(z, W1, b1, W2, b2, eps, out);
}